// round 1
// baseline (speedup 1.0000x reference)
#include <cuda_runtime.h>
#include <math.h>

// Problem-fixed shapes
#define B_ 1024
#define T_ 128

// Inter-layer activation buffers (allocation-free scratch).
__device__ float g_buf1[B_ * T_ * 128];  // layer1 out [B,T,128]
__device__ float g_buf2[B_ * T_ * 64];   // layer2 out [B,T,64]
__device__ float g_buf3[B_ * 32];        // layer3 out [B,32]

__device__ __forceinline__ float sigf(float x) { return 1.0f / (1.0f + expf(-x)); }

// One bidirectional LSTM layer. grid = (B/ROWS, 2 dirs), block = ROWS*U threads.
// Thread (r,u) owns output unit u of batch row (blockIdx.x*ROWS + r) and computes
// all 4 gates itself via gate-interleaved float4 weight reads from SMEM.
// SMEM layout: Wk_s[F][U][4] | Wr_s[U][U][4] | b_s[U][4] | xs[ROWS][F] | hs[ROWS][U]
template <int F, int U, int ROWS, bool SEQ>
__global__ void __launch_bounds__(ROWS * U) lstm_layer_kernel(
    const float* __restrict__ xin,   // [B, T, F]
    const float* __restrict__ Wkf, const float* __restrict__ Wrf, const float* __restrict__ bf,
    const float* __restrict__ Wkb, const float* __restrict__ Wrb, const float* __restrict__ bb,
    float* __restrict__ out)         // SEQ: [B, T, 2U]   else: [B, 2U]
{
    constexpr int G4 = 4 * U;
    constexpr int NT = ROWS * U;

    extern __shared__ float sm[];
    float* Wk_s = sm;                    // F * G4
    float* Wr_s = Wk_s + F * G4;         // U * G4
    float* b_s  = Wr_s + U * G4;         // G4
    float* xs   = b_s + G4;              // ROWS * F
    float* hs   = xs + ROWS * F;         // ROWS * U

    const int dir = blockIdx.y;          // 0 = forward, 1 = backward
    const float* Wk   = dir ? Wkb : Wkf;
    const float* Wr   = dir ? Wrb : Wrf;
    const float* bias = dir ? bb  : bf;

    const int tid = threadIdx.x;

    // Stage weights gate-interleaved: Wk_s[(f*U + u)*4 + g] = Wk[f*4U + g*U + u]
    for (int i = tid; i < F * G4; i += NT) {
        int f = i / G4, c = i % G4, u = c >> 2, g = c & 3;
        Wk_s[i] = Wk[f * G4 + g * U + u];
    }
    for (int i = tid; i < U * G4; i += NT) {
        int u2 = i / G4, c = i % G4, u = c >> 2, g = c & 3;
        Wr_s[i] = Wr[u2 * G4 + g * U + u];
    }
    for (int i = tid; i < G4; i += NT) {
        int u = i >> 2, g = i & 3;
        b_s[i] = bias[g * U + u];
    }
    for (int i = tid; i < ROWS * U; i += NT) hs[i] = 0.0f;

    const int r = tid / U;
    const int u = tid % U;
    const int b0 = blockIdx.x * ROWS;

    float cst = 0.0f;
    float hlast = 0.0f;

    __syncthreads();
    const float4 bv = ((const float4*)b_s)[u];
    const float4* __restrict__ wk4 = (const float4*)Wk_s;
    const float4* __restrict__ wr4 = (const float4*)Wr_s;

    for (int s = 0; s < T_; ++s) {
        const int t = dir ? (T_ - 1 - s) : s;

        // Stage this step's inputs for the ROWS batch rows.
        for (int i = tid; i < ROWS * F; i += NT) {
            int rr = i / F, ff = i % F;
            xs[i] = xin[((b0 + rr) * T_ + t) * F + ff];
        }
        __syncthreads();

        float ai = bv.x, af = bv.y, ag = bv.z, ao = bv.w;

        const float* __restrict__ xr = xs + r * F;
#pragma unroll 4
        for (int f = 0; f < F; ++f) {
            float v = xr[f];
            float4 w = wk4[f * U + u];
            ai += v * w.x; af += v * w.y; ag += v * w.z; ao += v * w.w;
        }
        const float* __restrict__ hr = hs + r * U;
#pragma unroll 4
        for (int u2 = 0; u2 < U; ++u2) {
            float v = hr[u2];
            float4 w = wr4[u2 * U + u];
            ai += v * w.x; af += v * w.y; ag += v * w.z; ao += v * w.w;
        }

        float ig = sigf(ai);
        float fg = sigf(af);
        float gg = tanhf(ag);
        float og = sigf(ao);
        cst = fg * cst + ig * gg;
        hlast = og * tanhf(cst);

        __syncthreads();  // all reads of old h complete before overwrite
        hs[r * U + u] = hlast;
        if (SEQ) {
            // backward output lands at original time index t (Keras re-reverses)
            out[((b0 + r) * T_ + t) * (2 * U) + dir * U + u] = hlast;
        }
    }
    if (!SEQ) {
        out[(b0 + r) * (2 * U) + dir * U + u] = hlast;
    }
}

// Final MLP head: relu(h @ d3_w + d3_b) @ cls_w + cls_b -> sigmoid. h: [B,32]
__global__ void head_kernel(const float* __restrict__ h3,
                            const float* __restrict__ d3w, const float* __restrict__ d3b,
                            const float* __restrict__ cw,  const float* __restrict__ cb,
                            float* __restrict__ out)
{
    int b = blockIdx.x * blockDim.x + threadIdx.x;
    if (b >= B_) return;

    float hv[32];
#pragma unroll
    for (int i = 0; i < 32; ++i) hv[i] = h3[b * 32 + i];

    float d[8];
#pragma unroll
    for (int j = 0; j < 8; ++j) {
        float a = d3b[j];
#pragma unroll
        for (int i = 0; i < 32; ++i) a += hv[i] * d3w[i * 8 + j];
        d[j] = a > 0.0f ? a : 0.0f;
    }
#pragma unroll
    for (int k = 0; k < 3; ++k) {
        float a = cb[k];
#pragma unroll
        for (int j = 0; j < 8; ++j) a += d[j] * cw[j * 3 + k];
        out[b * 3 + k] = 1.0f / (1.0f + expf(-a));
    }
}

static inline size_t lstm_smem(int F, int U, int ROWS) {
    return (size_t)(F * 4 * U + U * 4 * U + 4 * U + ROWS * F + ROWS * U) * sizeof(float);
}

extern "C" void kernel_launch(void* const* d_in, const int* in_sizes, int n_in,
                              void* d_out, int out_size)
{
    const float* x     = (const float*)d_in[0];
    const float* w1f_k = (const float*)d_in[1];
    const float* w1f_r = (const float*)d_in[2];
    const float* w1f_b = (const float*)d_in[3];
    const float* w1b_k = (const float*)d_in[4];
    const float* w1b_r = (const float*)d_in[5];
    const float* w1b_b = (const float*)d_in[6];
    const float* w2f_k = (const float*)d_in[7];
    const float* w2f_r = (const float*)d_in[8];
    const float* w2f_b = (const float*)d_in[9];
    const float* w2b_k = (const float*)d_in[10];
    const float* w2b_r = (const float*)d_in[11];
    const float* w2b_b = (const float*)d_in[12];
    const float* w3f_k = (const float*)d_in[13];
    const float* w3f_r = (const float*)d_in[14];
    const float* w3f_b = (const float*)d_in[15];
    const float* w3b_k = (const float*)d_in[16];
    const float* w3b_r = (const float*)d_in[17];
    const float* w3b_b = (const float*)d_in[18];
    const float* d3_w  = (const float*)d_in[19];
    const float* d3_b  = (const float*)d_in[20];
    const float* cls_w = (const float*)d_in[21];
    const float* cls_b = (const float*)d_in[22];

    float *b1, *b2, *b3;
    cudaGetSymbolAddress((void**)&b1, g_buf1);
    cudaGetSymbolAddress((void**)&b2, g_buf2);
    cudaGetSymbolAddress((void**)&b3, g_buf3);

    const size_t sm1 = lstm_smem(78, 64, 4);    // ~148.7 KB
    const size_t sm2 = lstm_smem(128, 32, 8);   // ~87.6 KB
    const size_t sm3 = lstm_smem(64, 16, 16);   // ~25.9 KB

    cudaFuncSetAttribute(lstm_layer_kernel<78, 64, 4, true>,
                         cudaFuncAttributeMaxDynamicSharedMemorySize, (int)sm1);
    cudaFuncSetAttribute(lstm_layer_kernel<128, 32, 8, true>,
                         cudaFuncAttributeMaxDynamicSharedMemorySize, (int)sm2);
    cudaFuncSetAttribute(lstm_layer_kernel<64, 16, 16, false>,
                         cudaFuncAttributeMaxDynamicSharedMemorySize, (int)sm3);

    // Layer 1: F=78 -> 2*64, ROWS=4 (256 thr), grid (256, 2)
    lstm_layer_kernel<78, 64, 4, true><<<dim3(B_ / 4, 2), 4 * 64, sm1>>>(
        x, w1f_k, w1f_r, w1f_b, w1b_k, w1b_r, w1b_b, b1);

    // Layer 2: F=128 -> 2*32, ROWS=8 (256 thr), grid (128, 2)
    lstm_layer_kernel<128, 32, 8, true><<<dim3(B_ / 8, 2), 8 * 32, sm2>>>(
        b1, w2f_k, w2f_r, w2f_b, w2b_k, w2b_r, w2b_b, b2);

    // Layer 3: F=64 -> 2*16 last-step only, ROWS=16 (256 thr), grid (64, 2)
    lstm_layer_kernel<64, 16, 16, false><<<dim3(B_ / 16, 2), 16 * 16, sm3>>>(
        b2, w3f_k, w3f_r, w3f_b, w3b_k, w3b_r, w3b_b, b3);

    // Head: [B,32] -> [B,3]
    head_kernel<<<(B_ + 255) / 256, 256>>>(b3, d3_w, d3_b, cls_w, cls_b, (float*)d_out);
}

// round 2
// speedup vs baseline: 2.8546x; 2.8546x over previous
#include <cuda_runtime.h>
#include <math.h>

// Problem-fixed shapes
#define B_ 1024
#define T_ 128

// Inter-layer activation buffers (allocation-free scratch).
__device__ float g_buf1[B_ * T_ * 128];  // layer1 out [B,T,128]
__device__ float g_buf2[B_ * T_ * 64];   // layer2 out [B,T,64]
__device__ float g_buf3[B_ * 32];        // layer3 out [B,32]

__device__ __forceinline__ float sigf(float x) {
    // 1/(1+e^-x) with fast exp + fast division (err ~1e-6, fine vs 1e-3 budget)
    return __fdividef(1.0f, 1.0f + __expf(-x));
}
__device__ __forceinline__ float tanhf_fast(float x) {
    // tanh(x) = 2/(1+e^-2x) - 1
    return __fdividef(2.0f, 1.0f + __expf(-2.0f * x)) - 1.0f;
}

// One bidirectional LSTM layer, FFMA-bound formulation.
// grid = (B/ROWS, 2 dirs), block = (ROWS/R)*U threads.
// Thread (rg,u) owns output unit u for R batch rows rg*R..rg*R+R-1: each 16B
// weight float4 (gate-interleaved i,f,g,o) feeds 4*R FFMAs. x and h are read
// as float4 broadcasts. h and x tiles are double-buffered (1 sync per step);
// next step's x is prefetched into registers to hide global latency.
// SMEM: Wk_s[FP][U][4] | Wr_s[U][U][4] | b_s[U][4] | xs0/xs1[ROWS][FP] | hs0/hs1[ROWS][U]
template <int F, int FP, int U, int ROWS, int R, bool SEQ>
__global__ void __launch_bounds__((ROWS / R) * U) lstm_layer_kernel(
    const float* __restrict__ xin,   // [B, T, F]
    const float* __restrict__ Wkf, const float* __restrict__ Wrf, const float* __restrict__ bf,
    const float* __restrict__ Wkb, const float* __restrict__ Wrb, const float* __restrict__ bb,
    float* __restrict__ out)         // SEQ: [B, T, 2U]   else: [B, 2U]
{
    constexpr int G4 = 4 * U;
    constexpr int NT = (ROWS / R) * U;
    constexpr int XS = ROWS * FP;
    constexpr int HS = ROWS * U;
    constexpr int NXLD = (ROWS * F + NT - 1) / NT;

    extern __shared__ float sm[];
    float* Wk_s = sm;                    // FP * G4
    float* Wr_s = Wk_s + FP * G4;        // U * G4
    float* b_s  = Wr_s + U * G4;         // G4
    float* xs0  = b_s + G4;              // XS
    float* xs1  = xs0 + XS;              // XS
    float* hs0  = xs1 + XS;              // HS
    float* hs1  = hs0 + HS;              // HS

    const int dir = blockIdx.y;          // 0 = forward, 1 = backward
    const float* Wk   = dir ? Wkb : Wkf;
    const float* Wr   = dir ? Wrb : Wrf;
    const float* bias = dir ? bb  : bf;

    const int tid = threadIdx.x;

    // Stage weights gate-interleaved: Wk_s[(f*U + u)*4 + g] = Wk[f*4U + g*U + u]
    for (int i = tid; i < FP * G4; i += NT) {
        int f = i / G4, c = i % G4, u = c >> 2, g = c & 3;
        Wk_s[i] = (f < F) ? Wk[f * G4 + g * U + u] : 0.0f;
    }
    for (int i = tid; i < U * G4; i += NT) {
        int u2 = i / G4, c = i % G4, u = c >> 2, g = c & 3;
        Wr_s[i] = Wr[u2 * G4 + g * U + u];
    }
    for (int i = tid; i < G4; i += NT) {
        b_s[i] = bias[(i & 3) * U + (i >> 2)];
    }
    for (int i = tid; i < HS; i += NT) { hs0[i] = 0.0f; hs1[i] = 0.0f; }
    for (int i = tid; i < XS; i += NT) { xs0[i] = 0.0f; xs1[i] = 0.0f; }  // zeros pad cols

    const int rg = tid / U;
    const int u  = tid % U;
    const int r0 = rg * R;
    const int b0 = blockIdx.x * ROWS;

    // Preload first timestep into xs0
    {
        const int t0 = dir ? (T_ - 1) : 0;
#pragma unroll
        for (int k = 0; k < NXLD; ++k) {
            int i = tid + k * NT;
            if (i < ROWS * F) {
                int rr = i / F, ff = i % F;
                xs0[rr * FP + ff] = xin[((b0 + rr) * T_ + t0) * F + ff];
            }
        }
    }
    __syncthreads();

    float c_st[R], hval[R];
#pragma unroll
    for (int j = 0; j < R; ++j) { c_st[j] = 0.0f; hval[j] = 0.0f; }

    const float4 bv = ((const float4*)b_s)[u];
    const float4* __restrict__ wk4 = (const float4*)Wk_s;
    const float4* __restrict__ wr4 = (const float4*)Wr_s;

    float* xs_c = xs0; float* xs_n = xs1;
    float* hs_c = hs0; float* hs_n = hs1;

    float pre[NXLD];

    for (int s = 0; s < T_; ++s) {
        const int t  = dir ? (T_ - 1 - s) : s;
        const int sn = (s + 1 < T_) ? (s + 1) : s;          // clamp on last step
        const int tn = dir ? (T_ - 1 - sn) : sn;

        // Prefetch next step's x into registers (overlaps with compute below).
#pragma unroll
        for (int k = 0; k < NXLD; ++k) {
            int i = tid + k * NT;
            if (i < ROWS * F) {
                int rr = i / F, ff = i % F;
                pre[k] = xin[((b0 + rr) * T_ + tn) * F + ff];
            }
        }

        float ai[R], afv[R], ag[R], ao[R];
#pragma unroll
        for (int j = 0; j < R; ++j) { ai[j] = bv.x; afv[j] = bv.y; ag[j] = bv.z; ao[j] = bv.w; }

        // Input projection: x[rows r0..r0+R-1] @ Wk
#pragma unroll 4
        for (int f4 = 0; f4 < FP / 4; ++f4) {
            float4 xv[R];
#pragma unroll
            for (int j = 0; j < R; ++j)
                xv[j] = *(const float4*)(xs_c + (r0 + j) * FP + f4 * 4);
#pragma unroll
            for (int q = 0; q < 4; ++q) {
                float4 w = wk4[(f4 * 4 + q) * U + u];
#pragma unroll
                for (int j = 0; j < R; ++j) {
                    float v = (&xv[j].x)[q];
                    ai[j] += v * w.x; afv[j] += v * w.y; ag[j] += v * w.z; ao[j] += v * w.w;
                }
            }
        }
        // Recurrent projection: h @ Wr
#pragma unroll 4
        for (int u4 = 0; u4 < U / 4; ++u4) {
            float4 hv[R];
#pragma unroll
            for (int j = 0; j < R; ++j)
                hv[j] = *(const float4*)(hs_c + (r0 + j) * U + u4 * 4);
#pragma unroll
            for (int q = 0; q < 4; ++q) {
                float4 w = wr4[(u4 * 4 + q) * U + u];
#pragma unroll
                for (int j = 0; j < R; ++j) {
                    float v = (&hv[j].x)[q];
                    ai[j] += v * w.x; afv[j] += v * w.y; ag[j] += v * w.z; ao[j] += v * w.w;
                }
            }
        }

#pragma unroll
        for (int j = 0; j < R; ++j) {
            float ig = sigf(ai[j]);
            float fg = sigf(afv[j]);
            float gg = tanhf_fast(ag[j]);
            float og = sigf(ao[j]);
            c_st[j] = fg * c_st[j] + ig * gg;
            hval[j] = og * tanhf_fast(c_st[j]);
            hs_n[(r0 + j) * U + u] = hval[j];
            if (SEQ)
                out[((size_t)(b0 + r0 + j) * T_ + t) * (2 * U) + dir * U + u] = hval[j];
        }

        // Commit prefetched x into the next buffer.
#pragma unroll
        for (int k = 0; k < NXLD; ++k) {
            int i = tid + k * NT;
            if (i < ROWS * F) {
                int rr = i / F, ff = i % F;
                xs_n[rr * FP + ff] = pre[k];
            }
        }
        __syncthreads();
        float* tmp;
        tmp = xs_c; xs_c = xs_n; xs_n = tmp;
        tmp = hs_c; hs_c = hs_n; hs_n = tmp;
    }

    if (!SEQ) {
#pragma unroll
        for (int j = 0; j < R; ++j)
            out[(b0 + r0 + j) * (2 * U) + dir * U + u] = hval[j];
    }
}

// Final MLP head: relu(h @ d3_w + d3_b) @ cls_w + cls_b -> sigmoid. h: [B,32]
__global__ void head_kernel(const float* __restrict__ h3,
                            const float* __restrict__ d3w, const float* __restrict__ d3b,
                            const float* __restrict__ cw,  const float* __restrict__ cb,
                            float* __restrict__ out)
{
    int b = blockIdx.x * blockDim.x + threadIdx.x;
    if (b >= B_) return;

    float hv[32];
#pragma unroll
    for (int i = 0; i < 32; ++i) hv[i] = h3[b * 32 + i];

    float d[8];
#pragma unroll
    for (int j = 0; j < 8; ++j) {
        float a = d3b[j];
#pragma unroll
        for (int i = 0; i < 32; ++i) a += hv[i] * d3w[i * 8 + j];
        d[j] = a > 0.0f ? a : 0.0f;
    }
#pragma unroll
    for (int k = 0; k < 3; ++k) {
        float a = cb[k];
#pragma unroll
        for (int j = 0; j < 8; ++j) a += d[j] * cw[j * 3 + k];
        out[b * 3 + k] = 1.0f / (1.0f + expf(-a));
    }
}

static inline size_t lstm_smem(int FP, int U, int ROWS) {
    return (size_t)(FP * 4 * U + U * 4 * U + 4 * U + 2 * ROWS * FP + 2 * ROWS * U) * sizeof(float);
}

extern "C" void kernel_launch(void* const* d_in, const int* in_sizes, int n_in,
                              void* d_out, int out_size)
{
    const float* x     = (const float*)d_in[0];
    const float* w1f_k = (const float*)d_in[1];
    const float* w1f_r = (const float*)d_in[2];
    const float* w1f_b = (const float*)d_in[3];
    const float* w1b_k = (const float*)d_in[4];
    const float* w1b_r = (const float*)d_in[5];
    const float* w1b_b = (const float*)d_in[6];
    const float* w2f_k = (const float*)d_in[7];
    const float* w2f_r = (const float*)d_in[8];
    const float* w2f_b = (const float*)d_in[9];
    const float* w2b_k = (const float*)d_in[10];
    const float* w2b_r = (const float*)d_in[11];
    const float* w2b_b = (const float*)d_in[12];
    const float* w3f_k = (const float*)d_in[13];
    const float* w3f_r = (const float*)d_in[14];
    const float* w3f_b = (const float*)d_in[15];
    const float* w3b_k = (const float*)d_in[16];
    const float* w3b_r = (const float*)d_in[17];
    const float* w3b_b = (const float*)d_in[18];
    const float* d3_w  = (const float*)d_in[19];
    const float* d3_b  = (const float*)d_in[20];
    const float* cls_w = (const float*)d_in[21];
    const float* cls_b = (const float*)d_in[22];

    float *b1, *b2, *b3;
    cudaGetSymbolAddress((void**)&b1, g_buf1);
    cudaGetSymbolAddress((void**)&b2, g_buf2);
    cudaGetSymbolAddress((void**)&b3, g_buf3);

    // L1: F=78 (pad 80), U=64, ROWS=16, R=4 -> 256 thr, grid (64,2)
    // L2: F=128,          U=32, ROWS=16, R=4 -> 128 thr, grid (64,2)
    // L3: F=64,           U=16, ROWS=16, R=2 -> 128 thr, grid (64,2)
    const size_t sm1 = lstm_smem(80, 64, 16);    // ~167 KB
    const size_t sm2 = lstm_smem(128, 32, 16);   // ~103 KB
    const size_t sm3 = lstm_smem(64, 16, 16);    // ~31 KB

    cudaFuncSetAttribute((const void*)lstm_layer_kernel<78, 80, 64, 16, 4, true>,
                         cudaFuncAttributeMaxDynamicSharedMemorySize, (int)sm1);
    cudaFuncSetAttribute((const void*)lstm_layer_kernel<128, 128, 32, 16, 4, true>,
                         cudaFuncAttributeMaxDynamicSharedMemorySize, (int)sm2);
    cudaFuncSetAttribute((const void*)lstm_layer_kernel<64, 64, 16, 16, 2, false>,
                         cudaFuncAttributeMaxDynamicSharedMemorySize, (int)sm3);

    lstm_layer_kernel<78, 80, 64, 16, 4, true><<<dim3(B_ / 16, 2), 256, sm1>>>(
        x, w1f_k, w1f_r, w1f_b, w1b_k, w1b_r, w1b_b, b1);

    lstm_layer_kernel<128, 128, 32, 16, 4, true><<<dim3(B_ / 16, 2), 128, sm2>>>(
        b1, w2f_k, w2f_r, w2f_b, w2b_k, w2b_r, w2b_b, b2);

    lstm_layer_kernel<64, 64, 16, 16, 2, false><<<dim3(B_ / 16, 2), 128, sm3>>>(
        b2, w3f_k, w3f_r, w3f_b, w3b_k, w3b_r, w3b_b, b3);

    head_kernel<<<(B_ + 255) / 256, 256>>>(b3, d3_w, d3_b, cls_w, cls_b, (float*)d_out);
}